// round 1
// baseline (speedup 1.0000x reference)
#include <cuda_runtime.h>

typedef unsigned long long ull;

#define D_MODEL 2048
#define N_STATE 256
#define RANK    64
#define LEVELS  8
#define MAX_T   16384

// ---- GEMM1: t = u @ F1   (M=T, K=2048, N=64) ----
#define TM1   128
#define KC1   32
#define NTHR1 128
#define NC1   (D_MODEL / KC1)

// ---- GEMM2: out = t @ Wcm + D*u  (M=T, K=64, N=2048) ----
#define TM2   128
#define TN2   128
#define NTHR2 256
#define SM2_TS (TM2 * 65)
#define SM2_BS (RANK * TN2)
#define SM2_FLOATS (SM2_TS + SM2_BS + TN2)

// scratch (static device globals: allowed; no allocation)
__device__ float g_E[RANK * RANK];
__device__ float g_F1[D_MODEL * RANK];
__device__ float g_t[MAX_T * RANK];

// ---- packed f32x2 helpers (FFMA2 path, 2 MAC/lane/instr) ----
__device__ __forceinline__ ull pk2(float lo, float hi) {
    ull r;
    asm("mov.b64 %0, {%1, %2};" : "=l"(r) : "f"(lo), "f"(hi));
    return r;
}
__device__ __forceinline__ void fma2(ull& d, ull a, ull b) {
    asm("fma.rn.f32x2 %0, %1, %2, %0;" : "+l"(d) : "l"(a), "l"(b));
}
__device__ __forceinline__ float2 upk2(ull v) {
    float2 f;
    asm("mov.b64 {%0, %1}, %2;" : "=f"(f.x), "=f"(f.y) : "l"(v));
    return f;
}

// =====================================================================
// Kernel 0: E = Wbs @ Butterfly @ Wcr   (64x64)
// Butterfly acts as state @ M; applying it to the ROWS of Wbs gives Wbs@M.
// Level lvl acts on bit position (7-lvl): stride = 128 >> lvl.
//   new0 = x0*A[0][0] + x1*A[1][0] ; new1 = x0*A[0][1] + x1*A[1][1]
// Process 32 rows of Wbs at a time so smem stays <= 48KB static.
// =====================================================================
__global__ void compute_E_kernel(const float* __restrict__ A_factors,
                                 const float* __restrict__ Wbs,
                                 const float* __restrict__ Wcr) {
    __shared__ float G[N_STATE * 32];   // G[n*32 + r_local]
    __shared__ float Af[LEVELS * 4];
    const int tid = threadIdx.x;
    if (tid < LEVELS * 4) Af[tid] = A_factors[tid];

    for (int half = 0; half < 2; half++) {
        __syncthreads();
        // load 32 rows of Wbs, transposed into G
        for (int i = tid; i < 32 * N_STATE; i += blockDim.x) {
            int r = i >> 8;       // 0..31
            int n = i & 255;
            G[n * 32 + r] = Wbs[(half * 32 + r) * N_STATE + n];
        }
        __syncthreads();
        for (int lvl = 0; lvl < LEVELS; lvl++) {
            const int stride = 128 >> lvl;
            const float a00 = Af[lvl * 4 + 0], a01 = Af[lvl * 4 + 1];
            const float a10 = Af[lvl * 4 + 2], a11 = Af[lvl * 4 + 3];
            for (int p = tid; p < 128 * 32; p += blockDim.x) {
                int r  = p & 31;
                int pi = p >> 5;                 // 0..127 pair index
                int low = pi & (stride - 1);
                int n0  = ((pi - low) << 1) | low;
                int n1  = n0 + stride;
                float x0 = G[n0 * 32 + r];
                float x1 = G[n1 * 32 + r];
                G[n0 * 32 + r] = x0 * a00 + x1 * a10;
                G[n1 * 32 + r] = x0 * a01 + x1 * a11;
            }
            __syncthreads();
        }
        // E rows [half*32, half*32+32) = G_rows @ Wcr
        for (int o = tid; o < 32 * RANK; o += blockDim.x) {
            int rl = o >> 6;
            int j  = o & 63;
            float acc = 0.f;
            for (int n = 0; n < N_STATE; n++)
                acc += G[n * 32 + rl] * Wcr[n * RANK + j];
            g_E[(half * 32 + rl) * RANK + j] = acc;
        }
    }
}

// =====================================================================
// Kernel 1: F1 = Wbr @ E   ([2048,64] x [64,64])
// =====================================================================
__global__ void compute_F1_kernel(const float* __restrict__ Wbr) {
    __shared__ float Es[RANK * RANK];
    const int tid = threadIdx.x;
    for (int i = tid; i < RANK * RANK; i += 256) Es[i] = g_E[i];
    __syncthreads();
    const int o   = blockIdx.x * 256 + tid;
    const int row = o >> 6;
    const int j   = o & 63;
    float acc = 0.f;
#pragma unroll
    for (int k = 0; k < RANK; k++)
        acc += Wbr[row * RANK + k] * Es[k * RANK + j];
    g_F1[o] = acc;
}

// =====================================================================
// Kernel 2: t = u @ F1   (M=T, K=2048, N=64)
// 128 threads/CTA, per-thread 8 rows x 8 cols, f32x2 accumulators over
// column pairs. Register-prefetched double buffering of the K chunks.
// =====================================================================
__global__ __launch_bounds__(NTHR1) void gemm1_kernel(const float* __restrict__ u) {
    __shared__ float Us[TM1 * 33];       // row-major, pad 33 -> conflict-free a reads
    __shared__ float Fs[KC1 * RANK];
    const int tid = threadIdx.x;
    const int tx = tid & 7;              // col group: {tx*4..+3} U {32+tx*4..+3}
    const int ty = tid >> 3;             // row group: 8 rows each
    const size_t row0 = (size_t)blockIdx.x * TM1;

    ull acc[32];
#pragma unroll
    for (int i = 0; i < 32; i++) acc[i] = 0ULL;

    float4 pu[8];
    float4 pf[4];

    // prefetch chunk 0
#pragma unroll
    for (int i = 0; i < 8; i++) {
        int idx = tid + i * NTHR1;
        int r = idx >> 3, c4 = idx & 7;
        pu[i] = *(const float4*)(u + (row0 + r) * D_MODEL + c4 * 4);
    }
#pragma unroll
    for (int i = 0; i < 4; i++) {
        int idx = tid + i * NTHR1;
        int kk = idx >> 4, c4 = idx & 15;
        pf[i] = *(const float4*)(g_F1 + kk * RANK + c4 * 4);
    }

    for (int nc = 0; nc < NC1; nc++) {
        __syncthreads();
        // regs -> smem
#pragma unroll
        for (int i = 0; i < 8; i++) {
            int idx = tid + i * NTHR1;
            int r = idx >> 3, c4 = idx & 7;
            float* d = &Us[r * 33 + c4 * 4];
            d[0] = pu[i].x; d[1] = pu[i].y; d[2] = pu[i].z; d[3] = pu[i].w;
        }
#pragma unroll
        for (int i = 0; i < 4; i++) {
            int idx = tid + i * NTHR1;
            int kk = idx >> 4, c4 = idx & 15;
            *(float4*)&Fs[kk * RANK + c4 * 4] = pf[i];
        }
        __syncthreads();
        // prefetch next chunk (overlaps with compute below)
        if (nc + 1 < NC1) {
            const int k0 = (nc + 1) * KC1;
#pragma unroll
            for (int i = 0; i < 8; i++) {
                int idx = tid + i * NTHR1;
                int r = idx >> 3, c4 = idx & 7;
                pu[i] = *(const float4*)(u + (row0 + r) * D_MODEL + k0 + c4 * 4);
            }
#pragma unroll
            for (int i = 0; i < 4; i++) {
                int idx = tid + i * NTHR1;
                int kk = idx >> 4, c4 = idx & 15;
                pf[i] = *(const float4*)(g_F1 + (size_t)(k0 + kk) * RANK + c4 * 4);
            }
        }
        // compute
#pragma unroll 8
        for (int k = 0; k < KC1; k++) {
            float4 bA = *(const float4*)&Fs[k * RANK + tx * 4];
            float4 bB = *(const float4*)&Fs[k * RANK + 32 + tx * 4];
            ull b0 = pk2(bA.x, bA.y), b1 = pk2(bA.z, bA.w);
            ull b2 = pk2(bB.x, bB.y), b3 = pk2(bB.z, bB.w);
#pragma unroll
            for (int i = 0; i < 8; i++) {
                float a = Us[(ty * 8 + i) * 33 + k];
                ull a2 = pk2(a, a);
                fma2(acc[i * 4 + 0], a2, b0);
                fma2(acc[i * 4 + 1], a2, b1);
                fma2(acc[i * 4 + 2], a2, b2);
                fma2(acc[i * 4 + 3], a2, b3);
            }
        }
    }

    // epilogue -> g_t
#pragma unroll
    for (int i = 0; i < 8; i++) {
        size_t row = row0 + ty * 8 + i;
        float2 c0 = upk2(acc[i * 4 + 0]);
        float2 c1 = upk2(acc[i * 4 + 1]);
        float2 c2 = upk2(acc[i * 4 + 2]);
        float2 c3 = upk2(acc[i * 4 + 3]);
        float4 v0 = make_float4(c0.x, c0.y, c1.x, c1.y);
        float4 v1 = make_float4(c2.x, c2.y, c3.x, c3.y);
        *(float4*)(g_t + row * RANK + tx * 4) = v0;
        *(float4*)(g_t + row * RANK + 32 + tx * 4) = v1;
    }
}

// =====================================================================
// Kernel 3: out = t @ Wcm + D*u   (M=T, K=64, N=2048)
// 256 threads/CTA, tile 128x128, K=64 fully staged in smem (one pass).
// =====================================================================
__global__ __launch_bounds__(NTHR2) void gemm2_kernel(const float* __restrict__ u,
                                                      const float* __restrict__ Wcm,
                                                      const float* __restrict__ Dv,
                                                      float* __restrict__ out) {
    extern __shared__ float sm[];
    float* Ts  = sm;                  // [128][65]
    float* Bs  = sm + SM2_TS;         // [64][128]
    float* Dsh = Bs + SM2_BS;         // [128]

    const int tid = threadIdx.x;
    const int tx = tid & 15;          // cols {tx*4..+3} U {64+tx*4..+3}
    const int ty = tid >> 4;          // 8 rows each
    const int ct = blockIdx.x & 15;   // D_MODEL/TN2 = 16 col tiles
    const int rt = blockIdx.x >> 4;
    const size_t row0 = (size_t)rt * TM2;
    const int col0 = ct * TN2;

    // load t tile [128 x 64]
#pragma unroll
    for (int i = 0; i < 8; i++) {
        int idx = tid + i * NTHR2;
        int r = idx >> 4, c4 = idx & 15;
        float4 v = *(const float4*)(g_t + (row0 + r) * RANK + c4 * 4);
        float* d = &Ts[r * 65 + c4 * 4];
        d[0] = v.x; d[1] = v.y; d[2] = v.z; d[3] = v.w;
    }
    // load Wcm tile [64 x 128]
#pragma unroll
    for (int i = 0; i < 8; i++) {
        int idx = tid + i * NTHR2;
        int kk = idx >> 5, c4 = idx & 31;
        *(float4*)&Bs[kk * TN2 + c4 * 4] =
            *(const float4*)(Wcm + (size_t)kk * D_MODEL + col0 + c4 * 4);
    }
    if (tid < TN2 / 4) {
        *(float4*)&Dsh[tid * 4] = *(const float4*)(Dv + col0 + tid * 4);
    }
    __syncthreads();

    ull acc[32];
#pragma unroll
    for (int i = 0; i < 32; i++) acc[i] = 0ULL;

#pragma unroll 8
    for (int k = 0; k < RANK; k++) {
        float4 bA = *(const float4*)&Bs[k * TN2 + tx * 4];
        float4 bB = *(const float4*)&Bs[k * TN2 + 64 + tx * 4];
        ull b0 = pk2(bA.x, bA.y), b1 = pk2(bA.z, bA.w);
        ull b2 = pk2(bB.x, bB.y), b3 = pk2(bB.z, bB.w);
#pragma unroll
        for (int i = 0; i < 8; i++) {
            float a = Ts[(ty * 8 + i) * 65 + k];
            ull a2 = pk2(a, a);
            fma2(acc[i * 4 + 0], a2, b0);
            fma2(acc[i * 4 + 1], a2, b1);
            fma2(acc[i * 4 + 2], a2, b2);
            fma2(acc[i * 4 + 3], a2, b3);
        }
    }

    // epilogue: out = acc + D * u
#pragma unroll
    for (int i = 0; i < 8; i++) {
        size_t row = row0 + ty * 8 + i;
        const float* urow = u + row * D_MODEL + col0;
        float* orow = out + row * D_MODEL + col0;
        float4 u0 = *(const float4*)(urow + tx * 4);
        float4 u1 = *(const float4*)(urow + 64 + tx * 4);
        float4 d0 = *(const float4*)&Dsh[tx * 4];
        float4 d1 = *(const float4*)&Dsh[64 + tx * 4];
        float2 a0 = upk2(acc[i * 4 + 0]), a1 = upk2(acc[i * 4 + 1]);
        float2 a2 = upk2(acc[i * 4 + 2]), a3 = upk2(acc[i * 4 + 3]);
        float4 o0 = make_float4(a0.x + d0.x * u0.x, a0.y + d0.y * u0.y,
                                a1.x + d0.z * u0.z, a1.y + d0.w * u0.w);
        float4 o1 = make_float4(a2.x + d1.x * u1.x, a2.y + d1.y * u1.y,
                                a3.x + d1.z * u1.z, a3.y + d1.w * u1.w);
        *(float4*)(orow + tx * 4) = o0;
        *(float4*)(orow + 64 + tx * 4) = o1;
    }
}

extern "C" void kernel_launch(void* const* d_in, const int* in_sizes, int n_in,
                              void* d_out, int out_size) {
    const float* u   = (const float*)d_in[0];
    const float* Af  = (const float*)d_in[1];
    const float* Wbr = (const float*)d_in[2];
    const float* Wbs = (const float*)d_in[3];
    const float* Wcr = (const float*)d_in[4];
    const float* Wcm = (const float*)d_in[5];
    const float* Dv  = (const float*)d_in[6];
    float* out = (float*)d_out;

    const int T = in_sizes[0] / D_MODEL;   // 16384

    cudaFuncSetAttribute(gemm2_kernel, cudaFuncAttributeMaxDynamicSharedMemorySize,
                         SM2_FLOATS * (int)sizeof(float));

    compute_E_kernel<<<1, 256>>>(Af, Wbs, Wcr);
    compute_F1_kernel<<<(D_MODEL * RANK) / 256, 256>>>(Wbr);
    gemm1_kernel<<<T / TM1, NTHR1>>>(u);
    gemm2_kernel<<<(T / TM2) * (D_MODEL / TN2), NTHR2,
                   SM2_FLOATS * (int)sizeof(float)>>>(u, Wcm, Dv, out);
}